// round 16
// baseline (speedup 1.0000x reference)
#include <cuda_runtime.h>
#include <cuda_bf16.h>
#include <cuda_fp16.h>
#include <cstdint>

// Problem constants (fixed shapes)
#define NTOK  4096      // B*S = 2*2048
#define DDIM  1024
#define WDIM  4096
#define SLOT  8
#define NLEAF 8         // 1 << TREE_DEPTH
#define NC    11        // SLOT + 3

// GEMM tiling: CTA 128(M) x 256(N), K-chunk 64, 512 threads (16 warps, 4x4)
#define TMM 128
#define TNN 256
#define KCC 64
#define GT  512
#define ABYTES (TMM * 128)            // 16 KB  (128 rows x 128B)
#define BBYTES (TNN * 128)            // 32 KB
#define OFF_A  0
#define OFF_B  (ABYTES)
#define STAGE  (ABYTES + BBYTES)      // 49152
#define NSTG   4
#define GSMEM  (NSTG * STAGE)         // 196608
#define NCH    (WDIM / KCC)           // 64

// Scratch (static device arrays — runtime alloc is forbidden)
__device__ __align__(128) float  g_wsel [WDIM * NLEAF * 12];  // 12-padded per leaf
__device__ __align__(128) float  g_slots[NTOK * SLOT];
__device__ __align__(128) __half g_a[(size_t)NTOK * WDIM];   // roots, fp16, [M][K]
__device__ __align__(128) __half g_b[(size_t)DDIM * WDIM];   // out_w^T, fp16, [N][K]

// ---------------------------------------------------------------------------
// PTX helpers (sm_80-era features only — no 'a'-suffix instructions)
// ---------------------------------------------------------------------------
__device__ __forceinline__ uint32_t smem_u32(const void* p) {
    uint32_t a;
    asm("{ .reg .u64 t; cvta.to.shared.u64 t, %1; cvt.u32.u64 %0, t; }"
        : "=r"(a) : "l"(p));
    return a;
}

__device__ __forceinline__ void cp16(uint32_t saddr, const void* g) {
    asm volatile("cp.async.cg.shared.global [%0], [%1], 16;"
                 :: "r"(saddr), "l"(g) : "memory");
}
#define CP_COMMIT() asm volatile("cp.async.commit_group;" ::: "memory")
#define CP_WAIT(n)  asm volatile("cp.async.wait_group %0;" :: "n"(n) : "memory")

__device__ __forceinline__ void ldsm_x4(uint32_t* r, uint32_t addr) {
    asm volatile("ldmatrix.sync.aligned.m8n8.x4.shared.b16 {%0,%1,%2,%3}, [%4];"
                 : "=r"(r[0]), "=r"(r[1]), "=r"(r[2]), "=r"(r[3]) : "r"(addr));
}

__device__ __forceinline__ void mma_fp16(float* c, const uint32_t* a,
                                         uint32_t b0, uint32_t b1) {
    asm volatile(
        "mma.sync.aligned.m16n8k16.row.col.f32.f16.f16.f32 "
        "{%0,%1,%2,%3}, {%4,%5,%6,%7}, {%8,%9}, {%0,%1,%2,%3};"
        : "+f"(c[0]), "+f"(c[1]), "+f"(c[2]), "+f"(c[3])
        : "r"(a[0]), "r"(a[1]), "r"(a[2]), "r"(a[3]), "r"(b0), "r"(b1));
}

// Accurate fast tanh: tanh(x) = 1 - 2/(exp(2x)+1)
__device__ __forceinline__ float tanh_fast(float x) {
    float e = __expf(2.0f * x);
    return 1.0f - __fdividef(2.0f, e + 1.0f);
}

// tanh from pre-scaled argument z' = 2*log2(e)*z : 4 instructions, 2 MUFU
__device__ __forceinline__ float tanh_prescaled(float zp) {
    float e, r;
    asm("ex2.approx.f32 %0, %1;" : "=f"(e) : "f"(zp));
    asm("rcp.approx.f32 %0, %1;" : "=f"(r) : "f"(e + 1.0f));
    return fmaf(-2.0f, r, 1.0f);
}

// ---------------------------------------------------------------------------
// Kernel 1: selector softmax + constant folding (12-padded output)
// ---------------------------------------------------------------------------
__global__ __launch_bounds__(256)
void prep_selector_kernel(const float* __restrict__ leaf_logits,
                          float* __restrict__ wsel) {
    int idx = blockIdx.x * blockDim.x + threadIdx.x;   // w*8 + leaf
    if (idx >= WDIM * NLEAF) return;
    const float* lg = leaf_logits + (size_t)idx * NC;

    float m = lg[0];
    #pragma unroll
    for (int c = 1; c < NC; c++) m = fmaxf(m, lg[c]);

    float e[NC];
    float s = 0.0f;
    #pragma unroll
    for (int c = 0; c < NC; c++) { e[c] = __expf(lg[c] - m); s += e[c]; }
    float inv = 1.0f / s;

    float* o = wsel + (size_t)idx * 12;
    #pragma unroll
    for (int c = 0; c < SLOT; c++) o[c] = e[c] * inv;
    o[8]  = (e[10] - e[8]) * inv;   // folded constants [-1, 0, 1]
    o[9]  = 0.0f;
    o[10] = 0.0f;
    o[11] = 0.0f;
}

// ---------------------------------------------------------------------------
// Kernel 2: slots = tanh(hidden @ slot_w + slot_b).
// One warp per 4 consecutive tokens: slot_w loads amortized 4x
// (L1-bandwidth was the binding constraint at 1 token/warp).
// Per-token accumulation order identical to before (j = lane + 32*i).
// ---------------------------------------------------------------------------
__global__ __launch_bounds__(256)
void slots_kernel(const float* __restrict__ hidden,
                  const float* __restrict__ slot_w,
                  const float* __restrict__ slot_b,
                  float* __restrict__ slots) {
    int gw   = (blockIdx.x * blockDim.x + threadIdx.x) >> 5;   // warp id
    int lane = threadIdx.x & 31;
    int t0 = gw * 4;
    if (t0 >= NTOK) return;

    const float* h0 = hidden + (size_t)(t0 + 0) * DDIM;
    const float* h1 = hidden + (size_t)(t0 + 1) * DDIM;
    const float* h2 = hidden + (size_t)(t0 + 2) * DDIM;
    const float* h3 = hidden + (size_t)(t0 + 3) * DDIM;

    float acc[4][SLOT];
    #pragma unroll
    for (int t = 0; t < 4; t++)
        #pragma unroll
        for (int s = 0; s < SLOT; s++) acc[t][s] = 0.0f;

    for (int j = lane; j < DDIM; j += 32) {
        float hv0 = h0[j], hv1 = h1[j], hv2 = h2[j], hv3 = h3[j];
        float4 w0 = *reinterpret_cast<const float4*>(slot_w + (size_t)j * SLOT);
        float4 w1 = *reinterpret_cast<const float4*>(slot_w + (size_t)j * SLOT + 4);
        acc[0][0] = fmaf(hv0, w0.x, acc[0][0]);
        acc[0][1] = fmaf(hv0, w0.y, acc[0][1]);
        acc[0][2] = fmaf(hv0, w0.z, acc[0][2]);
        acc[0][3] = fmaf(hv0, w0.w, acc[0][3]);
        acc[0][4] = fmaf(hv0, w1.x, acc[0][4]);
        acc[0][5] = fmaf(hv0, w1.y, acc[0][5]);
        acc[0][6] = fmaf(hv0, w1.z, acc[0][6]);
        acc[0][7] = fmaf(hv0, w1.w, acc[0][7]);
        acc[1][0] = fmaf(hv1, w0.x, acc[1][0]);
        acc[1][1] = fmaf(hv1, w0.y, acc[1][1]);
        acc[1][2] = fmaf(hv1, w0.z, acc[1][2]);
        acc[1][3] = fmaf(hv1, w0.w, acc[1][3]);
        acc[1][4] = fmaf(hv1, w1.x, acc[1][4]);
        acc[1][5] = fmaf(hv1, w1.y, acc[1][5]);
        acc[1][6] = fmaf(hv1, w1.z, acc[1][6]);
        acc[1][7] = fmaf(hv1, w1.w, acc[1][7]);
        acc[2][0] = fmaf(hv2, w0.x, acc[2][0]);
        acc[2][1] = fmaf(hv2, w0.y, acc[2][1]);
        acc[2][2] = fmaf(hv2, w0.z, acc[2][2]);
        acc[2][3] = fmaf(hv2, w0.w, acc[2][3]);
        acc[2][4] = fmaf(hv2, w1.x, acc[2][4]);
        acc[2][5] = fmaf(hv2, w1.y, acc[2][5]);
        acc[2][6] = fmaf(hv2, w1.z, acc[2][6]);
        acc[2][7] = fmaf(hv2, w1.w, acc[2][7]);
        acc[3][0] = fmaf(hv3, w0.x, acc[3][0]);
        acc[3][1] = fmaf(hv3, w0.y, acc[3][1]);
        acc[3][2] = fmaf(hv3, w0.z, acc[3][2]);
        acc[3][3] = fmaf(hv3, w0.w, acc[3][3]);
        acc[3][4] = fmaf(hv3, w1.x, acc[3][4]);
        acc[3][5] = fmaf(hv3, w1.y, acc[3][5]);
        acc[3][6] = fmaf(hv3, w1.z, acc[3][6]);
        acc[3][7] = fmaf(hv3, w1.w, acc[3][7]);
    }
    #pragma unroll
    for (int off = 16; off > 0; off >>= 1) {
        #pragma unroll
        for (int t = 0; t < 4; t++)
            #pragma unroll
            for (int s = 0; s < SLOT; s++)
                acc[t][s] += __shfl_down_sync(0xffffffffu, acc[t][s], off);
    }
    if (lane == 0) {
        #pragma unroll
        for (int t = 0; t < 4; t++)
            #pragma unroll
            for (int s = 0; s < SLOT; s++)
                slots[(size_t)(t0 + t) * SLOT + s] = tanh_fast(acc[t][s] + slot_b[s]);
    }
}

// ---------------------------------------------------------------------------
// Kernel 3: roots -> fp16, [token][w] row-major.
// CTA: 64 w x 256 tokens. lane = token; each lane handles tokens
// (t, t+32, t+64, t+96): leaf-weight broadcast LDS amortized 4x,
// 4 independent MUFU chains. Output staged in smem (66-half rows:
// conflict-free STS.16), flushed via 4x LDS.32 + STG.128.
// ---------------------------------------------------------------------------
#define RW   64     // w per CTA
#define RT   256    // tokens per CTA
#define ROW_H 66    // s_out row stride in halves (33 words -> conflict-free STS.16)
__global__ __launch_bounds__(256)
void roots_kernel(const float* __restrict__ wsel,
                  const float* __restrict__ slots,
                  const float* __restrict__ np,
                  __half* __restrict__ A) {
    __shared__ float  s_wsel[RW * 96];
    __shared__ __align__(16) __half s_out[128 * ROW_H];

    const int tid  = threadIdx.x;
    const int lane = tid & 31;
    const int wrp  = tid >> 5;            // 0..7
    const int w0   = blockIdx.x * RW;
    const int tb0  = blockIdx.y * RT;

    // load wsel tile once: 64 rows x 96 floats = 1536 float4
    {
        const float4* gw = reinterpret_cast<const float4*>(wsel + (size_t)w0 * 96);
        float4* sw = reinterpret_cast<float4*>(s_wsel);
        #pragma unroll
        for (int i = 0; i < 6; i++) sw[tid + i * 256] = gw[tid + i * 256];
    }

    // node coefficients, pre-scaled by 2*log2(e) (folds tanh's exp scaling)
    const float SC  = 2.8853900817779268f;
    const float a1  = (np[0] + np[3]) * SC;   // (lw + dw)
    const float a2  = (np[1] - np[3]) * SC;   // (rw - dw)
    const float pws = np[2] * SC;
    const float nbs = np[4] * SC;
    __syncthreads();

    #pragma unroll
    for (int tt = 0; tt < RT / 128; tt++) {
        const int tok0 = tb0 + tt * 128 + lane;

        // 4 tokens' slots (L1/L2-cached; reused by all w-tiles)
        float sl[4][SLOT];
        #pragma unroll
        for (int t = 0; t < 4; t++) {
            const float* sp = slots + (size_t)(tok0 + t * 32) * SLOT;
            float4 s0 = __ldg(reinterpret_cast<const float4*>(sp));
            float4 s1 = __ldg(reinterpret_cast<const float4*>(sp + 4));
            sl[t][0] = s0.x; sl[t][1] = s0.y; sl[t][2] = s0.z; sl[t][3] = s0.w;
            sl[t][4] = s1.x; sl[t][5] = s1.y; sl[t][6] = s1.z; sl[t][7] = s1.w;
        }

        for (int wi = 0; wi < RW / 8; wi++) {
            const int wl = wrp * 8 + wi;                 // local w index (warp-uniform)
            const float* wp = &s_wsel[wl * 96];

            float v[4][NLEAF];
            #pragma unroll
            for (int l = 0; l < NLEAF; l++) {
                float4 wv0 = *reinterpret_cast<const float4*>(wp + l * 12);
                float4 wv1 = *reinterpret_cast<const float4*>(wp + l * 12 + 4);
                float4 wv2 = *reinterpret_cast<const float4*>(wp + l * 12 + 8); // .x = bias
                #pragma unroll
                for (int t = 0; t < 4; t++) {
                    float a = fmaf(wv0.x, sl[t][0], wv2.x);
                    a = fmaf(wv0.y, sl[t][1], a);
                    a = fmaf(wv0.z, sl[t][2], a);
                    a = fmaf(wv0.w, sl[t][3], a);
                    a = fmaf(wv1.x, sl[t][4], a);
                    a = fmaf(wv1.y, sl[t][5], a);
                    a = fmaf(wv1.z, sl[t][6], a);
                    a = fmaf(wv1.w, sl[t][7], a);
                    v[t][l] = a;
                }
            }

            // 3-level tree for 4 tokens (independent MUFU chains)
            #pragma unroll
            for (int n = 4; n >= 1; n >>= 1) {
                #pragma unroll
                for (int j = 0; j < 4; j++) {
                    if (j < n) {
                        #pragma unroll
                        for (int t = 0; t < 4; t++) {
                            float L = v[t][2 * j], R = v[t][2 * j + 1];
                            float z = fmaf(pws, L * R, nbs);
                            z = fmaf(a2, R, z);
                            z = fmaf(a1, L, z);
                            v[t][j] = tanh_prescaled(z);
                        }
                    }
                }
            }
            #pragma unroll
            for (int t = 0; t < 4; t++)
                s_out[(lane + t * 32) * ROW_H + wl] = __float2half(v[t][0]);
        }
        __syncthreads();

        // flush: 128 rows x 64 halves (128B) coalesced.
        // Row byte stride = 132 (4B-aligned only) -> gather via 4x LDS.32.
        {
            const uint32_t* sp = reinterpret_cast<const uint32_t*>(s_out);
            #pragma unroll
            for (int f = 0; f < 4; f++) {
                int idx = tid + f * 256;             // 0..1023
                int row = idx >> 3;                  // 0..127
                int seg = idx & 7;                   // 0..7 (x16 bytes)
                int e = row * 33 + seg * 4;          // word index (132B row = 33 words)
                uint4 val;
                val.x = sp[e + 0];
                val.y = sp[e + 1];
                val.z = sp[e + 2];
                val.w = sp[e + 3];
                *reinterpret_cast<uint4*>(A + (size_t)(tb0 + tt * 128 + row) * WDIM + w0 + seg * 8) = val;
            }
        }
        __syncthreads();
    }
}

// ---------------------------------------------------------------------------
// Kernel 3b: transpose out_w [K][N] fp32 -> B [N][K] fp16
// ---------------------------------------------------------------------------
__global__ __launch_bounds__(256)
void transpose_kernel(const float* __restrict__ W,
                      __half* __restrict__ B) {
    __shared__ float t[32][33];
    int tx = threadIdx.x, ty = threadIdx.y;       // block (32, 8)
    int k0 = blockIdx.x * 32, n0 = blockIdx.y * 32;

    #pragma unroll
    for (int i = 0; i < 4; i++)
        t[ty + 8 * i][tx] = W[(size_t)(k0 + ty + 8 * i) * DDIM + n0 + tx];
    __syncthreads();

    #pragma unroll
    for (int i = 0; i < 4; i++)
        B[(size_t)(n0 + ty + 8 * i) * WDIM + k0 + tx] = __float2half(t[tx][ty + 8 * i]);
}

// ---------------------------------------------------------------------------
// Kernel 4: mma.sync fp16 GEMM.  C[4096,1024] = A B^T + bias  (fp32 accum)
// CTA 128x256, K-chunk 64, 4-stage cp.async pipeline, 16 warps (4x4).
// ---------------------------------------------------------------------------
__global__ void __launch_bounds__(GT, 1)
gemm_mma_kernel(const __half* __restrict__ A,
                const __half* __restrict__ B,
                const float* __restrict__ bias,
                float* __restrict__ C) {
    extern __shared__ char smem[];
    const uint32_t sbase = smem_u32(smem);
    const int tid  = threadIdx.x;
    const int lane = tid & 31;
    const int w    = tid >> 5;        // 0..15
    const int wm   = w & 3;           // M warp coord (x32)
    const int wn   = w >> 2;          // N warp coord (x64)
    const int brow = blockIdx.y * TMM;
    const int bcol = blockIdx.x * TNN;
    const int K = WDIM;

    float acc[2][8][4];
    #pragma unroll
    for (int a = 0; a < 2; a++)
        #pragma unroll
        for (int b = 0; b < 8; b++)
            #pragma unroll
            for (int c = 0; c < 4; c++) acc[a][b][c] = 0.0f;

    // ldmatrix lane->address precomputation
    const int lr   = lane & 7;
    const int ls8  = (lane >> 3) & 1;       // A: +8 rows    B: +1 k-chunk
    const int lhi  = lane >> 4;             // A: +1 k-chunk B: +8 rows
    const int arow0 = wm * 32 + lr + ls8 * 8;
    const int brow0 = wn * 64 + lr + lhi * 8;
    const uint32_t aswz = arow0 & 7;
    const uint32_t bswz = brow0 & 7;
    uint32_t arowb[2], browb[4];
    #pragma unroll
    for (int mt = 0; mt < 2; mt++) arowb[mt] = (uint32_t)(arow0 + mt * 16) << 7;
    #pragma unroll
    for (int i = 0; i < 4; i++)    browb[i] = (uint32_t)(brow0 + i * 16) << 7;

    // stage loader: A rows (brow..+127), B rows (bcol..+255), k0..k0+63
    auto load_stage = [&](int ci) {
        const uint32_t sb = sbase + (ci % NSTG) * STAGE;
        const int k0 = ci * KCC;
        #pragma unroll
        for (int it = 0; it < 2; it++) {
            int idx = tid + it * GT;          // 0..1023
            int r = idx >> 3, c = idx & 7;
            uint32_t sw = ((uint32_t)r << 7) + (((uint32_t)(c ^ (r & 7))) << 4);
            cp16(sb + OFF_A + sw, A + (size_t)(brow + r) * K + k0 + c * 8);
        }
        #pragma unroll
        for (int it = 0; it < 4; it++) {
            int idx = tid + it * GT;          // 0..2047
            int r = idx >> 3, c = idx & 7;
            uint32_t sw = ((uint32_t)r << 7) + (((uint32_t)(c ^ (r & 7))) << 4);
            cp16(sb + OFF_B + sw, B + (size_t)(bcol + r) * K + k0 + c * 8);
        }
    };

    load_stage(0); CP_COMMIT();
    load_stage(1); CP_COMMIT();
    load_stage(2); CP_COMMIT();

    for (int i = 0; i < NCH; i++) {
        CP_WAIT(2);            // stage i landed (this thread's view)
        __syncthreads();       // visible to all; all warps done with stage i-1

        if (i + 3 < NCH) { load_stage(i + 3); CP_COMMIT(); }

        const uint32_t sb = sbase + (i % NSTG) * STAGE;
        #pragma unroll
        for (int s = 0; s < 4; s++) {
            uint32_t ach = (((uint32_t)(2 * s + lhi)) ^ aswz) << 4;
            uint32_t bch = (((uint32_t)(2 * s + ls8)) ^ bswz) << 4;
            uint32_t af[2][4], bf[4][4];
            #pragma unroll
            for (int mt = 0; mt < 2; mt++)
                ldsm_x4(af[mt], sb + OFF_A + arowb[mt] + ach);
            #pragma unroll
            for (int bt = 0; bt < 4; bt++)
                ldsm_x4(bf[bt], sb + OFF_B + browb[bt] + bch);
            #pragma unroll
            for (int mt = 0; mt < 2; mt++)
                #pragma unroll
                for (int bt = 0; bt < 4; bt++) {
                    mma_fp16(acc[mt][2 * bt + 0], af[mt], bf[bt][0], bf[bt][1]);
                    mma_fp16(acc[mt][2 * bt + 1], af[mt], bf[bt][2], bf[bt][3]);
                }
        }
    }

    // Epilogue: acc -> C + bias
    const int r0 = lane >> 2;
    const int c0 = (lane & 3) * 2;
    #pragma unroll
    for (int mt = 0; mt < 2; mt++) {
        int grow = brow + wm * 32 + mt * 16 + r0;
        #pragma unroll
        for (int half = 0; half < 2; half++) {
            float* crow = C + (size_t)(grow + half * 8) * DDIM;
            #pragma unroll
            for (int nt = 0; nt < 8; nt++) {
                int gc = bcol + wn * 64 + nt * 8 + c0;
                float2 o;
                o.x = acc[mt][nt][half * 2 + 0] + bias[gc];
                o.y = acc[mt][nt][half * 2 + 1] + bias[gc + 1];
                *reinterpret_cast<float2*>(crow + gc) = o;
            }
        }
    }
}

// ---------------------------------------------------------------------------
// Launch.  Inputs: hidden, slot_w, slot_b, leaf_logits, node_params, out_w, out_b
// ---------------------------------------------------------------------------
extern "C" void kernel_launch(void* const* d_in, const int* in_sizes, int n_in,
                              void* d_out, int out_size) {
    const float* hidden      = (const float*)d_in[0];
    const float* slot_w      = (const float*)d_in[1];
    const float* slot_b      = (const float*)d_in[2];
    const float* leaf_logits = (const float*)d_in[3];
    const float* node_params = (const float*)d_in[4];
    const float* out_w       = (const float*)d_in[5];
    const float* out_b       = (const float*)d_in[6];
    float* out = (float*)d_out;

    float* wsel;  cudaGetSymbolAddress((void**)&wsel,  g_wsel);
    float* slots; cudaGetSymbolAddress((void**)&slots, g_slots);
    __half *A, *B;
    cudaGetSymbolAddress((void**)&A, g_a);
    cudaGetSymbolAddress((void**)&B, g_b);

    cudaFuncSetAttribute(gemm_mma_kernel,
                         cudaFuncAttributeMaxDynamicSharedMemorySize, GSMEM);

    // 1) selector softmax + constant folding (12-padded)
    prep_selector_kernel<<<(WDIM * NLEAF + 255) / 256, 256>>>(leaf_logits, wsel);

    // 2) slots (4 tokens per warp)
    slots_kernel<<<(NTOK / 4 * 32 + 255) / 256, 256>>>(hidden, slot_w, slot_b, slots);

    // 3b) transpose out_w -> fp16 [N][K]
    {
        dim3 grid(WDIM / 32, DDIM / 32);
        transpose_kernel<<<grid, dim3(32, 8)>>>(out_w, B);
    }

    // 3) roots -> fp16 [M][K]
    {
        dim3 grid(WDIM / RW, NTOK / RT);
        roots_kernel<<<grid, 256>>>(wsel, slots, node_params, A);
    }

    // 4) tensor-core GEMM + bias
    {
        dim3 grid(DDIM / TNN, NTOK / TMM);
        gemm_mma_kernel<<<grid, GT, GSMEM>>>(A, B, out_b, out);
    }
}

// round 17
// speedup vs baseline: 1.0075x; 1.0075x over previous
#include <cuda_runtime.h>
#include <cuda_bf16.h>
#include <cuda_fp16.h>
#include <cstdint>

// Problem constants (fixed shapes)
#define NTOK  4096      // B*S = 2*2048
#define DDIM  1024
#define WDIM  4096
#define SLOT  8
#define NLEAF 8         // 1 << TREE_DEPTH
#define NC    11        // SLOT + 3

// GEMM tiling: CTA 128(M) x 256(N), K-chunk 64, 512 threads (16 warps, 4x4)
#define TMM 128
#define TNN 256
#define KCC 64
#define GT  512
#define ABYTES (TMM * 128)            // 16 KB  (128 rows x 128B)
#define BBYTES (TNN * 128)            // 32 KB
#define OFF_A  0
#define OFF_B  (ABYTES)
#define STAGE  (ABYTES + BBYTES)      // 49152
#define NSTG   4
#define GSMEM  (NSTG * STAGE)         // 196608
#define NCH    (WDIM / KCC)           // 64

// Scratch (static device arrays — runtime alloc is forbidden)
__device__ __align__(128) float  g_wsel [WDIM * NLEAF * 12];  // 12-padded per leaf
__device__ __align__(128) float  g_slots[NTOK * SLOT];
__device__ __align__(128) __half g_a[(size_t)NTOK * WDIM];   // roots, fp16, [M][K]
__device__ __align__(128) __half g_b[(size_t)DDIM * WDIM];   // out_w^T, fp16, [N][K]

// ---------------------------------------------------------------------------
// PTX helpers (sm_80-era features only — no 'a'-suffix instructions)
// ---------------------------------------------------------------------------
__device__ __forceinline__ uint32_t smem_u32(const void* p) {
    uint32_t a;
    asm("{ .reg .u64 t; cvta.to.shared.u64 t, %1; cvt.u32.u64 %0, t; }"
        : "=r"(a) : "l"(p));
    return a;
}

__device__ __forceinline__ void cp16(uint32_t saddr, const void* g) {
    asm volatile("cp.async.cg.shared.global [%0], [%1], 16;"
                 :: "r"(saddr), "l"(g) : "memory");
}
#define CP_COMMIT() asm volatile("cp.async.commit_group;" ::: "memory")
#define CP_WAIT(n)  asm volatile("cp.async.wait_group %0;" :: "n"(n) : "memory")

__device__ __forceinline__ void ldsm_x4(uint32_t* r, uint32_t addr) {
    asm volatile("ldmatrix.sync.aligned.m8n8.x4.shared.b16 {%0,%1,%2,%3}, [%4];"
                 : "=r"(r[0]), "=r"(r[1]), "=r"(r[2]), "=r"(r[3]) : "r"(addr));
}

__device__ __forceinline__ void mma_fp16(float* c, const uint32_t* a,
                                         uint32_t b0, uint32_t b1) {
    asm volatile(
        "mma.sync.aligned.m16n8k16.row.col.f32.f16.f16.f32 "
        "{%0,%1,%2,%3}, {%4,%5,%6,%7}, {%8,%9}, {%0,%1,%2,%3};"
        : "+f"(c[0]), "+f"(c[1]), "+f"(c[2]), "+f"(c[3])
        : "r"(a[0]), "r"(a[1]), "r"(a[2]), "r"(a[3]), "r"(b0), "r"(b1));
}

// Accurate fast tanh: tanh(x) = 1 - 2/(exp(2x)+1)
__device__ __forceinline__ float tanh_fast(float x) {
    float e = __expf(2.0f * x);
    return 1.0f - __fdividef(2.0f, e + 1.0f);
}

// tanh from pre-scaled argument z' = 2*log2(e)*z : 4 instructions, 2 MUFU
__device__ __forceinline__ float tanh_prescaled(float zp) {
    float e, r;
    asm("ex2.approx.f32 %0, %1;" : "=f"(e) : "f"(zp));
    asm("rcp.approx.f32 %0, %1;" : "=f"(r) : "f"(e + 1.0f));
    return fmaf(-2.0f, r, 1.0f);
}

// ---------------------------------------------------------------------------
// Kernel 1: selector softmax + constant folding (12-padded output)
// ---------------------------------------------------------------------------
__global__ __launch_bounds__(256)
void prep_selector_kernel(const float* __restrict__ leaf_logits,
                          float* __restrict__ wsel) {
    int idx = blockIdx.x * blockDim.x + threadIdx.x;   // w*8 + leaf
    if (idx >= WDIM * NLEAF) return;
    const float* lg = leaf_logits + (size_t)idx * NC;

    float m = lg[0];
    #pragma unroll
    for (int c = 1; c < NC; c++) m = fmaxf(m, lg[c]);

    float e[NC];
    float s = 0.0f;
    #pragma unroll
    for (int c = 0; c < NC; c++) { e[c] = __expf(lg[c] - m); s += e[c]; }
    float inv = 1.0f / s;

    float* o = wsel + (size_t)idx * 12;
    #pragma unroll
    for (int c = 0; c < SLOT; c++) o[c] = e[c] * inv;
    o[8]  = (e[10] - e[8]) * inv;   // folded constants [-1, 0, 1]
    o[9]  = 0.0f;
    o[10] = 0.0f;
    o[11] = 0.0f;
}

// ---------------------------------------------------------------------------
// Kernel 2: slots = tanh(hidden @ slot_w + slot_b).
// One warp per 2 consecutive tokens: slot_w loads amortized 2x while keeping
// 2048 warps (~14/SM) for load-latency cover.  (4 tokens/warp collapsed
// occupancy to ~7 warps/SM and regressed — R16 post-mortem.)
// Per-token accumulation order identical (j = lane + 32*i).
// ---------------------------------------------------------------------------
__global__ __launch_bounds__(256)
void slots_kernel(const float* __restrict__ hidden,
                  const float* __restrict__ slot_w,
                  const float* __restrict__ slot_b,
                  float* __restrict__ slots) {
    int gw   = (blockIdx.x * blockDim.x + threadIdx.x) >> 5;   // warp id
    int lane = threadIdx.x & 31;
    int t0 = gw * 2;
    if (t0 >= NTOK) return;

    const float* h0 = hidden + (size_t)(t0 + 0) * DDIM;
    const float* h1 = hidden + (size_t)(t0 + 1) * DDIM;

    float acc[2][SLOT];
    #pragma unroll
    for (int t = 0; t < 2; t++)
        #pragma unroll
        for (int s = 0; s < SLOT; s++) acc[t][s] = 0.0f;

    for (int j = lane; j < DDIM; j += 32) {
        float hv0 = h0[j], hv1 = h1[j];
        float4 w0 = *reinterpret_cast<const float4*>(slot_w + (size_t)j * SLOT);
        float4 w1 = *reinterpret_cast<const float4*>(slot_w + (size_t)j * SLOT + 4);
        acc[0][0] = fmaf(hv0, w0.x, acc[0][0]);
        acc[0][1] = fmaf(hv0, w0.y, acc[0][1]);
        acc[0][2] = fmaf(hv0, w0.z, acc[0][2]);
        acc[0][3] = fmaf(hv0, w0.w, acc[0][3]);
        acc[0][4] = fmaf(hv0, w1.x, acc[0][4]);
        acc[0][5] = fmaf(hv0, w1.y, acc[0][5]);
        acc[0][6] = fmaf(hv0, w1.z, acc[0][6]);
        acc[0][7] = fmaf(hv0, w1.w, acc[0][7]);
        acc[1][0] = fmaf(hv1, w0.x, acc[1][0]);
        acc[1][1] = fmaf(hv1, w0.y, acc[1][1]);
        acc[1][2] = fmaf(hv1, w0.z, acc[1][2]);
        acc[1][3] = fmaf(hv1, w0.w, acc[1][3]);
        acc[1][4] = fmaf(hv1, w1.x, acc[1][4]);
        acc[1][5] = fmaf(hv1, w1.y, acc[1][5]);
        acc[1][6] = fmaf(hv1, w1.z, acc[1][6]);
        acc[1][7] = fmaf(hv1, w1.w, acc[1][7]);
    }
    #pragma unroll
    for (int off = 16; off > 0; off >>= 1) {
        #pragma unroll
        for (int t = 0; t < 2; t++)
            #pragma unroll
            for (int s = 0; s < SLOT; s++)
                acc[t][s] += __shfl_down_sync(0xffffffffu, acc[t][s], off);
    }
    if (lane == 0) {
        #pragma unroll
        for (int t = 0; t < 2; t++)
            #pragma unroll
            for (int s = 0; s < SLOT; s++)
                slots[(size_t)(t0 + t) * SLOT + s] = tanh_fast(acc[t][s] + slot_b[s]);
    }
}

// ---------------------------------------------------------------------------
// Kernel 3: roots -> fp16, [token][w] row-major.
// CTA: 64 w x 256 tokens. lane = token; each lane handles tokens
// (t, t+32, t+64, t+96): leaf-weight broadcast LDS amortized 4x,
// 4 independent MUFU chains. Output staged in smem (66-half rows:
// conflict-free STS.16), flushed via 4x LDS.32 + STG.128.
// ---------------------------------------------------------------------------
#define RW   64     // w per CTA
#define RT   256    // tokens per CTA
#define ROW_H 66    // s_out row stride in halves (33 words -> conflict-free STS.16)
__global__ __launch_bounds__(256)
void roots_kernel(const float* __restrict__ wsel,
                  const float* __restrict__ slots,
                  const float* __restrict__ np,
                  __half* __restrict__ A) {
    __shared__ float  s_wsel[RW * 96];
    __shared__ __align__(16) __half s_out[128 * ROW_H];

    const int tid  = threadIdx.x;
    const int lane = tid & 31;
    const int wrp  = tid >> 5;            // 0..7
    const int w0   = blockIdx.x * RW;
    const int tb0  = blockIdx.y * RT;

    // load wsel tile once: 64 rows x 96 floats = 1536 float4
    {
        const float4* gw = reinterpret_cast<const float4*>(wsel + (size_t)w0 * 96);
        float4* sw = reinterpret_cast<float4*>(s_wsel);
        #pragma unroll
        for (int i = 0; i < 6; i++) sw[tid + i * 256] = gw[tid + i * 256];
    }

    // node coefficients, pre-scaled by 2*log2(e) (folds tanh's exp scaling)
    const float SC  = 2.8853900817779268f;
    const float a1  = (np[0] + np[3]) * SC;   // (lw + dw)
    const float a2  = (np[1] - np[3]) * SC;   // (rw - dw)
    const float pws = np[2] * SC;
    const float nbs = np[4] * SC;
    __syncthreads();

    #pragma unroll
    for (int tt = 0; tt < RT / 128; tt++) {
        const int tok0 = tb0 + tt * 128 + lane;

        // 4 tokens' slots (L1/L2-cached; reused by all w-tiles)
        float sl[4][SLOT];
        #pragma unroll
        for (int t = 0; t < 4; t++) {
            const float* sp = slots + (size_t)(tok0 + t * 32) * SLOT;
            float4 s0 = __ldg(reinterpret_cast<const float4*>(sp));
            float4 s1 = __ldg(reinterpret_cast<const float4*>(sp + 4));
            sl[t][0] = s0.x; sl[t][1] = s0.y; sl[t][2] = s0.z; sl[t][3] = s0.w;
            sl[t][4] = s1.x; sl[t][5] = s1.y; sl[t][6] = s1.z; sl[t][7] = s1.w;
        }

        for (int wi = 0; wi < RW / 8; wi++) {
            const int wl = wrp * 8 + wi;                 // local w index (warp-uniform)
            const float* wp = &s_wsel[wl * 96];

            float v[4][NLEAF];
            #pragma unroll
            for (int l = 0; l < NLEAF; l++) {
                float4 wv0 = *reinterpret_cast<const float4*>(wp + l * 12);
                float4 wv1 = *reinterpret_cast<const float4*>(wp + l * 12 + 4);
                float4 wv2 = *reinterpret_cast<const float4*>(wp + l * 12 + 8); // .x = bias
                #pragma unroll
                for (int t = 0; t < 4; t++) {
                    float a = fmaf(wv0.x, sl[t][0], wv2.x);
                    a = fmaf(wv0.y, sl[t][1], a);
                    a = fmaf(wv0.z, sl[t][2], a);
                    a = fmaf(wv0.w, sl[t][3], a);
                    a = fmaf(wv1.x, sl[t][4], a);
                    a = fmaf(wv1.y, sl[t][5], a);
                    a = fmaf(wv1.z, sl[t][6], a);
                    a = fmaf(wv1.w, sl[t][7], a);
                    v[t][l] = a;
                }
            }

            // 3-level tree for 4 tokens (independent MUFU chains)
            #pragma unroll
            for (int n = 4; n >= 1; n >>= 1) {
                #pragma unroll
                for (int j = 0; j < 4; j++) {
                    if (j < n) {
                        #pragma unroll
                        for (int t = 0; t < 4; t++) {
                            float L = v[t][2 * j], R = v[t][2 * j + 1];
                            float z = fmaf(pws, L * R, nbs);
                            z = fmaf(a2, R, z);
                            z = fmaf(a1, L, z);
                            v[t][j] = tanh_prescaled(z);
                        }
                    }
                }
            }
            #pragma unroll
            for (int t = 0; t < 4; t++)
                s_out[(lane + t * 32) * ROW_H + wl] = __float2half(v[t][0]);
        }
        __syncthreads();

        // flush: 128 rows x 64 halves (128B) coalesced.
        // Row byte stride = 132 (4B-aligned only) -> gather via 4x LDS.32.
        {
            const uint32_t* sp = reinterpret_cast<const uint32_t*>(s_out);
            #pragma unroll
            for (int f = 0; f < 4; f++) {
                int idx = tid + f * 256;             // 0..1023
                int row = idx >> 3;                  // 0..127
                int seg = idx & 7;                   // 0..7 (x16 bytes)
                int e = row * 33 + seg * 4;          // word index (132B row = 33 words)
                uint4 val;
                val.x = sp[e + 0];
                val.y = sp[e + 1];
                val.z = sp[e + 2];
                val.w = sp[e + 3];
                *reinterpret_cast<uint4*>(A + (size_t)(tb0 + tt * 128 + row) * WDIM + w0 + seg * 8) = val;
            }
        }
        __syncthreads();
    }
}

// ---------------------------------------------------------------------------
// Kernel 3b: transpose out_w [K][N] fp32 -> B [N][K] fp16
// ---------------------------------------------------------------------------
__global__ __launch_bounds__(256)
void transpose_kernel(const float* __restrict__ W,
                      __half* __restrict__ B) {
    __shared__ float t[32][33];
    int tx = threadIdx.x, ty = threadIdx.y;       // block (32, 8)
    int k0 = blockIdx.x * 32, n0 = blockIdx.y * 32;

    #pragma unroll
    for (int i = 0; i < 4; i++)
        t[ty + 8 * i][tx] = W[(size_t)(k0 + ty + 8 * i) * DDIM + n0 + tx];
    __syncthreads();

    #pragma unroll
    for (int i = 0; i < 4; i++)
        B[(size_t)(n0 + ty + 8 * i) * WDIM + k0 + tx] = __float2half(t[tx][ty + 8 * i]);
}

// ---------------------------------------------------------------------------
// Kernel 4: mma.sync fp16 GEMM.  C[4096,1024] = A B^T + bias  (fp32 accum)
// CTA 128x256, K-chunk 64, 4-stage cp.async pipeline, 16 warps (4x4).
// ---------------------------------------------------------------------------
__global__ void __launch_bounds__(GT, 1)
gemm_mma_kernel(const __half* __restrict__ A,
                const __half* __restrict__ B,
                const float* __restrict__ bias,
                float* __restrict__ C) {
    extern __shared__ char smem[];
    const uint32_t sbase = smem_u32(smem);
    const int tid  = threadIdx.x;
    const int lane = tid & 31;
    const int w    = tid >> 5;        // 0..15
    const int wm   = w & 3;           // M warp coord (x32)
    const int wn   = w >> 2;          // N warp coord (x64)
    const int brow = blockIdx.y * TMM;
    const int bcol = blockIdx.x * TNN;
    const int K = WDIM;

    float acc[2][8][4];
    #pragma unroll
    for (int a = 0; a < 2; a++)
        #pragma unroll
        for (int b = 0; b < 8; b++)
            #pragma unroll
            for (int c = 0; c < 4; c++) acc[a][b][c] = 0.0f;

    // ldmatrix lane->address precomputation
    const int lr   = lane & 7;
    const int ls8  = (lane >> 3) & 1;       // A: +8 rows    B: +1 k-chunk
    const int lhi  = lane >> 4;             // A: +1 k-chunk B: +8 rows
    const int arow0 = wm * 32 + lr + ls8 * 8;
    const int brow0 = wn * 64 + lr + lhi * 8;
    const uint32_t aswz = arow0 & 7;
    const uint32_t bswz = brow0 & 7;
    uint32_t arowb[2], browb[4];
    #pragma unroll
    for (int mt = 0; mt < 2; mt++) arowb[mt] = (uint32_t)(arow0 + mt * 16) << 7;
    #pragma unroll
    for (int i = 0; i < 4; i++)    browb[i] = (uint32_t)(brow0 + i * 16) << 7;

    // stage loader: A rows (brow..+127), B rows (bcol..+255), k0..k0+63
    auto load_stage = [&](int ci) {
        const uint32_t sb = sbase + (ci % NSTG) * STAGE;
        const int k0 = ci * KCC;
        #pragma unroll
        for (int it = 0; it < 2; it++) {
            int idx = tid + it * GT;          // 0..1023
            int r = idx >> 3, c = idx & 7;
            uint32_t sw = ((uint32_t)r << 7) + (((uint32_t)(c ^ (r & 7))) << 4);
            cp16(sb + OFF_A + sw, A + (size_t)(brow + r) * K + k0 + c * 8);
        }
        #pragma unroll
        for (int it = 0; it < 4; it++) {
            int idx = tid + it * GT;          // 0..2047
            int r = idx >> 3, c = idx & 7;
            uint32_t sw = ((uint32_t)r << 7) + (((uint32_t)(c ^ (r & 7))) << 4);
            cp16(sb + OFF_B + sw, B + (size_t)(bcol + r) * K + k0 + c * 8);
        }
    };

    load_stage(0); CP_COMMIT();
    load_stage(1); CP_COMMIT();
    load_stage(2); CP_COMMIT();

    for (int i = 0; i < NCH; i++) {
        CP_WAIT(2);            // stage i landed (this thread's view)
        __syncthreads();       // visible to all; all warps done with stage i-1

        if (i + 3 < NCH) { load_stage(i + 3); CP_COMMIT(); }

        const uint32_t sb = sbase + (i % NSTG) * STAGE;
        #pragma unroll
        for (int s = 0; s < 4; s++) {
            uint32_t ach = (((uint32_t)(2 * s + lhi)) ^ aswz) << 4;
            uint32_t bch = (((uint32_t)(2 * s + ls8)) ^ bswz) << 4;
            uint32_t af[2][4], bf[4][4];
            #pragma unroll
            for (int mt = 0; mt < 2; mt++)
                ldsm_x4(af[mt], sb + OFF_A + arowb[mt] + ach);
            #pragma unroll
            for (int bt = 0; bt < 4; bt++)
                ldsm_x4(bf[bt], sb + OFF_B + browb[bt] + bch);
            #pragma unroll
            for (int mt = 0; mt < 2; mt++)
                #pragma unroll
                for (int bt = 0; bt < 4; bt++) {
                    mma_fp16(acc[mt][2 * bt + 0], af[mt], bf[bt][0], bf[bt][1]);
                    mma_fp16(acc[mt][2 * bt + 1], af[mt], bf[bt][2], bf[bt][3]);
                }
        }
    }

    // Epilogue: acc -> C + bias
    const int r0 = lane >> 2;
    const int c0 = (lane & 3) * 2;
    #pragma unroll
    for (int mt = 0; mt < 2; mt++) {
        int grow = brow + wm * 32 + mt * 16 + r0;
        #pragma unroll
        for (int half = 0; half < 2; half++) {
            float* crow = C + (size_t)(grow + half * 8) * DDIM;
            #pragma unroll
            for (int nt = 0; nt < 8; nt++) {
                int gc = bcol + wn * 64 + nt * 8 + c0;
                float2 o;
                o.x = acc[mt][nt][half * 2 + 0] + bias[gc];
                o.y = acc[mt][nt][half * 2 + 1] + bias[gc + 1];
                *reinterpret_cast<float2*>(crow + gc) = o;
            }
        }
    }
}

// ---------------------------------------------------------------------------
// Launch.  Inputs: hidden, slot_w, slot_b, leaf_logits, node_params, out_w, out_b
// ---------------------------------------------------------------------------
extern "C" void kernel_launch(void* const* d_in, const int* in_sizes, int n_in,
                              void* d_out, int out_size) {
    const float* hidden      = (const float*)d_in[0];
    const float* slot_w      = (const float*)d_in[1];
    const float* slot_b      = (const float*)d_in[2];
    const float* leaf_logits = (const float*)d_in[3];
    const float* node_params = (const float*)d_in[4];
    const float* out_w       = (const float*)d_in[5];
    const float* out_b       = (const float*)d_in[6];
    float* out = (float*)d_out;

    float* wsel;  cudaGetSymbolAddress((void**)&wsel,  g_wsel);
    float* slots; cudaGetSymbolAddress((void**)&slots, g_slots);
    __half *A, *B;
    cudaGetSymbolAddress((void**)&A, g_a);
    cudaGetSymbolAddress((void**)&B, g_b);

    cudaFuncSetAttribute(gemm_mma_kernel,
                         cudaFuncAttributeMaxDynamicSharedMemorySize, GSMEM);

    // 1) selector softmax + constant folding (12-padded)
    prep_selector_kernel<<<(WDIM * NLEAF + 255) / 256, 256>>>(leaf_logits, wsel);

    // 2) slots (2 tokens per warp)
    slots_kernel<<<(NTOK / 2 * 32 + 255) / 256, 256>>>(hidden, slot_w, slot_b, slots);

    // 3b) transpose out_w -> fp16 [N][K]
    {
        dim3 grid(WDIM / 32, DDIM / 32);
        transpose_kernel<<<grid, dim3(32, 8)>>>(out_w, B);
    }

    // 3) roots -> fp16 [M][K]
    {
        dim3 grid(WDIM / RW, NTOK / RT);
        roots_kernel<<<grid, 256>>>(wsel, slots, node_params, A);
    }

    // 4) tensor-core GEMM + bias
    {
        dim3 grid(DDIM / TNN, NTOK / TMM);
        gemm_mma_kernel<<<grid, GT, GSMEM>>>(A, B, out_b, out);
    }
}